// round 4
// baseline (speedup 1.0000x reference)
#include <cuda_runtime.h>
#include <cstdint>

// SparseAdam via inverted index (counting sort) + single fused streaming pass.
//
// Inputs: 0 idx i32[N], 1 grad f32[N,128], 2 emb f32[V,128], 3 step f32[V],
//         4 mem f32[V,128], 5 pow f32[V,128]
// Output: new_emb[V,128] | new_step[V] | new_mem[V,128] | new_pow[V,128]
//
// Pipeline: memset -> hist -> lookback-scan (writes {start,cnt} meta) ->
//           scatter_ids -> fused update (3.63 GB streaming floor).

#define DD 128
#define MAXE (1 << 21)
#define SCAN_BS 256
#define SCAN_PT 16
#define SCAN_TILE (SCAN_BS * SCAN_PT)   // 4096
#define MAX_SCAN_BLOCKS 1024

__device__ int  g_counts[MAXE];
__device__ int  g_offsets[MAXE];     // scatter cursor
__device__ int2 g_meta[MAXE];        // {start, cnt} for the update pass
__device__ int  g_rowids[MAXE];
__device__ unsigned long long g_desc[MAX_SCAN_BLOCKS];

// ---------------------------------------------------------------------------
__global__ void hist_k(const int* __restrict__ idx, int N) {
    const int n4 = N >> 2;
    const int stride = gridDim.x * blockDim.x;
    const int4* idx4 = (const int4*)idx;
    for (int i = blockIdx.x * blockDim.x + threadIdx.x; i < n4; i += stride) {
        int4 v = __ldg(idx4 + i);
        atomicAdd(&g_counts[v.x], 1);
        atomicAdd(&g_counts[v.y], 1);
        atomicAdd(&g_counts[v.z], 1);
        atomicAdd(&g_counts[v.w], 1);
    }
    for (int i = (n4 << 2) + blockIdx.x * blockDim.x + threadIdx.x; i < N; i += stride)
        atomicAdd(&g_counts[__ldg(idx + i)], 1);
}

// ---------------------------------------------------------------------------
// Single-pass exclusive scan (decoupled lookback). counts -> offsets + meta.
// ---------------------------------------------------------------------------
__global__ void scan_lb_k(int V) {
    const int bid = blockIdx.x;
    const int t = threadIdx.x;
    const int lane = t & 31;
    const int wid = t >> 5;
    const int base = bid * SCAN_TILE + t * SCAN_PT;

    int c[SCAN_PT];
    int v[SCAN_PT];
    int s = 0;
    #pragma unroll
    for (int i = 0; i < SCAN_PT; i++) {
        c[i] = (base + i < V) ? g_counts[base + i] : 0;
        v[i] = s;
        s += c[i];
    }

    int incl = s;
    #pragma unroll
    for (int d = 1; d < 32; d <<= 1) {
        int u = __shfl_up_sync(0xffffffffu, incl, d);
        if (lane >= d) incl += u;
    }

    __shared__ int wsum[SCAN_BS / 32];
    __shared__ int woff[SCAN_BS / 32];
    __shared__ int sh_total;
    __shared__ int sh_prefix;
    if (lane == 31) wsum[wid] = incl;
    __syncthreads();
    if (t < SCAN_BS / 32) {
        int x = wsum[t];
        int ss = x;
        #pragma unroll
        for (int d = 1; d < SCAN_BS / 32; d <<= 1) {
            int u = __shfl_up_sync(0xffu, ss, d);
            if (t >= d) ss += u;
        }
        woff[t] = ss - x;
        if (t == (SCAN_BS / 32) - 1) sh_total = ss;
    }
    __syncthreads();
    const int total = sh_total;

    if (t == 0) {
        if (bid == 0) {
            atomicExch(&g_desc[0],
                       (2ULL << 62) | (unsigned long long)(unsigned)total);
            sh_prefix = 0;
        } else {
            atomicExch(&g_desc[bid],
                       (1ULL << 62) | (unsigned long long)(unsigned)total);
            int prefix = 0;
            int j = bid - 1;
            while (true) {
                unsigned long long d;
                do {
                    d = atomicAdd(&g_desc[j], 0ULL);
                } while ((d >> 62) == 0ULL);
                prefix += (int)(unsigned)(d & 0xffffffffULL);
                if ((d >> 62) == 2ULL) break;
                j--;
            }
            atomicExch(&g_desc[bid],
                       (2ULL << 62) | (unsigned long long)(unsigned)(total + prefix));
            sh_prefix = prefix;
        }
    }
    __syncthreads();

    const int excl_thread = sh_prefix + woff[wid] + (incl - s);
    #pragma unroll
    for (int i = 0; i < SCAN_PT; i++) {
        if (base + i < V) {
            int start = excl_thread + v[i];
            g_offsets[base + i] = start;
            g_meta[base + i] = make_int2(start, c[i]);
        }
    }
}

// ---------------------------------------------------------------------------
__global__ void scatter_ids_k(const int* __restrict__ idx, int N) {
    const int n4 = N >> 2;
    const int stride = gridDim.x * blockDim.x;
    const int4* idx4 = (const int4*)idx;
    for (int i = blockIdx.x * blockDim.x + threadIdx.x; i < n4; i += stride) {
        int4 v = __ldg(idx4 + i);
        int b = i << 2;
        g_rowids[atomicAdd(&g_offsets[v.x], 1)] = b;
        g_rowids[atomicAdd(&g_offsets[v.y], 1)] = b + 1;
        g_rowids[atomicAdd(&g_offsets[v.z], 1)] = b + 2;
        g_rowids[atomicAdd(&g_offsets[v.w], 1)] = b + 3;
    }
    for (int i = (n4 << 2) + blockIdx.x * blockDim.x + threadIdx.x; i < N; i += stride)
        g_rowids[atomicAdd(&g_offsets[__ldg(idx + i)], 1)] = i;
}

// ---------------------------------------------------------------------------
// Fused gather + Adam update. One warp per vocab row, float4 per lane.
// Gather is 4-wide branchless (speculative dup loads weighted by 0/1) for MLP.
// ---------------------------------------------------------------------------
__global__ void __launch_bounds__(256, 6)
sadam_update_k(const float4* __restrict__ grad,
               const float4* __restrict__ emb,
               const float*  __restrict__ step_in,
               const float4* __restrict__ mem,
               const float4* __restrict__ pw,
               float4* __restrict__ out_emb,
               float*  __restrict__ out_step,
               float4* __restrict__ out_mem,
               float4* __restrict__ out_pow,
               int V) {
    const long gtid = (long)blockIdx.x * blockDim.x + threadIdx.x;
    const long row  = gtid >> 5;
    if (row >= V) return;
    const int  lane = (int)(gtid & 31);
    const long i4   = row * (DD / 4) + lane;

    const int2  meta = __ldg(&g_meta[row]);     // {start, cnt}
    const float st   = __ldg(step_in + row);
    const int   cnt  = meta.y;

    float4 e = __ldcs(emb + i4);
    float4 m = __ldcs(mem + i4);
    float4 p = __ldcs(pw  + i4);

    float4 ne, nm, np;
    float  nstep;

    if (cnt > 0) {
        const int start = meta.x;
        float4 gs = make_float4(0.f, 0.f, 0.f, 0.f);
        for (int jb = 0; jb < cnt; jb += 4) {
            const int rem = cnt - jb;               // >= 1, warp-uniform
            const int r0 = __ldg(&g_rowids[start + jb]);
            const int r1 = (rem > 1) ? __ldg(&g_rowids[start + jb + 1]) : r0;
            const int r2 = (rem > 2) ? __ldg(&g_rowids[start + jb + 2]) : r0;
            const int r3 = (rem > 3) ? __ldg(&g_rowids[start + jb + 3]) : r0;
            const float w1 = (rem > 1) ? 1.f : 0.f;
            const float w2 = (rem > 2) ? 1.f : 0.f;
            const float w3 = (rem > 3) ? 1.f : 0.f;
            float4 g0 = __ldcs(grad + (long)r0 * (DD / 4) + lane);
            float4 g1 = __ldcs(grad + (long)r1 * (DD / 4) + lane);
            float4 g2 = __ldcs(grad + (long)r2 * (DD / 4) + lane);
            float4 g3 = __ldcs(grad + (long)r3 * (DD / 4) + lane);
            gs.x += g0.x; gs.x = fmaf(w1, g1.x, gs.x); gs.x = fmaf(w2, g2.x, gs.x); gs.x = fmaf(w3, g3.x, gs.x);
            gs.y += g0.y; gs.y = fmaf(w1, g1.y, gs.y); gs.y = fmaf(w2, g2.y, gs.y); gs.y = fmaf(w3, g3.y, gs.y);
            gs.z += g0.z; gs.z = fmaf(w1, g1.z, gs.z); gs.z = fmaf(w2, g2.z, gs.z); gs.z = fmaf(w3, g3.z, gs.z);
            gs.w += g0.w; gs.w = fmaf(w1, g1.w, gs.w); gs.w = fmaf(w2, g2.w, gs.w); gs.w = fmaf(w3, g3.w, gs.w);
        }
        nstep = st + 1.f;
        const float inv = 1.f / (float)cnt;
        const float d1 = 1.f - exp2f(nstep * -0.15200309344504997f);   // 1-0.9^s
        const float d2 = 1.f - exp2f(nstep * -0.0014434169010128458f); // 1-0.999^s
        const float c1  = 0.001f / d1;
        const float id2 = 1.f / d2;

        #define ADAM1(GS, M, P, E, NM, NP, NE)                       \
        {                                                             \
            float g = (GS) * inv;                                     \
            NM = 0.9f * (M) + 0.1f * g;                               \
            NP = 0.999f * (P) + 0.001f * (g * g);                     \
            float stdv = c1 * NM / (sqrtf(NP * id2) + 1e-8f);         \
            NE = (E) - stdv;                                          \
        }
        ADAM1(gs.x, m.x, p.x, e.x, nm.x, np.x, ne.x)
        ADAM1(gs.y, m.y, p.y, e.y, nm.y, np.y, ne.y)
        ADAM1(gs.z, m.z, p.z, e.z, nm.z, np.z, ne.z)
        ADAM1(gs.w, m.w, p.w, e.w, nm.w, np.w, ne.w)
        #undef ADAM1
    } else {
        nstep = st;
        ne = e; nm = m; np = p;
    }

    __stcs(out_emb + i4, ne);
    __stcs(out_mem + i4, nm);
    __stcs(out_pow + i4, np);
    if (lane == 0) out_step[row] = nstep;
}

// ---------------------------------------------------------------------------
extern "C" void kernel_launch(void* const* d_in, const int* in_sizes, int n_in,
                              void* d_out, int out_size) {
    const int*   idx  = (const int*)  d_in[0];
    const float* grad = (const float*)d_in[1];
    const float* emb  = (const float*)d_in[2];
    const float* step = (const float*)d_in[3];
    const float* mem  = (const float*)d_in[4];
    const float* pw   = (const float*)d_in[5];

    const int N = in_sizes[0];
    const int V = in_sizes[3];

    float* out      = (float*)d_out;
    float* out_emb  = out;
    float* out_step = out_emb + (long)V * DD;
    float* out_mem  = out_step + V;
    float* out_pow  = out_mem + (long)V * DD;

    void* counts_ptr = nullptr;
    void* desc_ptr   = nullptr;
    cudaGetSymbolAddress(&counts_ptr, g_counts);
    cudaGetSymbolAddress(&desc_ptr, g_desc);
    cudaMemsetAsync(counts_ptr, 0, (size_t)V * sizeof(int));
    cudaMemsetAsync(desc_ptr, 0, sizeof(unsigned long long) * MAX_SCAN_BLOCKS);

    hist_k<<<592, 256>>>(idx, N);

    const int nb = (V + SCAN_TILE - 1) / SCAN_TILE;
    scan_lb_k<<<nb, SCAN_BS>>>(V);

    scatter_ids_k<<<592, 256>>>(idx, N);

    {
        const long threads = (long)V * 32;
        const int  blocks  = (int)((threads + 255) / 256);
        sadam_update_k<<<blocks, 256>>>((const float4*)grad, (const float4*)emb,
                                        step, (const float4*)mem, (const float4*)pw,
                                        (float4*)out_emb, out_step,
                                        (float4*)out_mem, (float4*)out_pow, V);
    }
}